// round 7
// baseline (speedup 1.0000x reference)
#include <cuda_runtime.h>
#include <math.h>

#define NN 100000
#define EE 800000
#define DOUT 47
#define BCAP 64
#define CHK 25600          // pipeline chunk (multiple of 256 and 16)

// Scratch (allocation-free rule: static device globals).
// g_h / g_h2 have one extra row (index NN) used as an all-zero gather target
// for bucket padding.
__device__ float g_h [(size_t)(NN + 1) * 64];
__device__ float g_h2[(size_t)(NN + 1) * 64];
__device__ float g_agg[(size_t)NN * 64];
__device__ int   g_deg[NN];          // after pad_kernel: deg rounded up to 8
__device__ int   g_bkt[(size_t)NN * BCAP];
__device__ int   g_idx64;

// ---------------------------------------------------------------------------
// Packed fp32x2 FMA (Blackwell FFMA2 — only reachable via PTX)
// ---------------------------------------------------------------------------
__device__ __forceinline__ void ffma2(unsigned long long& acc,
                                      unsigned long long a,
                                      unsigned long long b) {
    asm("fma.rn.f32x2 %0, %1, %2, %0;" : "+l"(acc) : "l"(a), "l"(b));
}
__device__ __forceinline__ unsigned long long pack2(float x) {
    unsigned long long r;
    asm("mov.b64 %0, {%1, %2};" : "=l"(r) : "f"(x), "f"(x));
    return r;
}

// ---------------------------------------------------------------------------
// zero degree array + detect edge dtype + zero the padding rows of g_h/g_h2
// ---------------------------------------------------------------------------
__global__ void zero_detect_kernel(const void* ei) {
    int i = blockIdx.x * blockDim.x + threadIdx.x;
    if (i < NN) g_deg[i] = 0;
    if (blockIdx.x == 0) {
        __shared__ int bad;
        if (threadIdx.x == 0) bad = 0;
        __syncthreads();
        const long long* p = (const long long*)ei;
        for (int j = threadIdx.x; j < 4096; j += blockDim.x) {
            long long v = p[j];
            if (v < 0 || v >= NN) bad = 1;
        }
        __syncthreads();
        if (threadIdx.x == 0) g_idx64 = bad ? 0 : 1;
    }
    if (blockIdx.x == 1 && threadIdx.x < 64) {
        g_h [(size_t)NN * 64 + threadIdx.x] = 0.f;
        g_h2[(size_t)NN * 64 + threadIdx.x] = 0.f;
    }
}

// ---------------------------------------------------------------------------
// Bucket fill: bkt[dst][pos++] = src
// ---------------------------------------------------------------------------
__global__ void bucket_fill_kernel(const void* ei) {
    int e = blockIdx.x * blockDim.x + threadIdx.x;
    if (e >= EE) return;
    int src, dst;
    if (g_idx64) {
        const long long* p = (const long long*)ei;
        src = (int)p[e];
        dst = (int)p[EE + e];
    } else {
        const int* p = (const int*)ei;
        src = p[e];
        dst = p[EE + e];
    }
    int pos = atomicAdd(&g_deg[dst], 1);
    if (pos < BCAP) g_bkt[(size_t)dst * BCAP + pos] = src;
}

// ---------------------------------------------------------------------------
// Pad each bucket to a multiple of 8 with sentinel NN (zero row); store deg8.
// ---------------------------------------------------------------------------
__global__ void pad_kernel() {
    int i = blockIdx.x * blockDim.x + threadIdx.x;
    if (i >= NN) return;
    int d  = min(g_deg[i], BCAP);
    int d8 = (d + 7) & ~7;          // <= 64 since BCAP multiple of 8
    int* bp = &g_bkt[(size_t)i * BCAP];
    for (int j = d; j < d8; j++) bp[j] = NN;
    g_deg[i] = d8;
}

// ---------------------------------------------------------------------------
// Phase-2 mini-GEMM: out[row0..row0+256, 0..DP) = xs[256,64] @ ws[64,DP]
// ---------------------------------------------------------------------------
template <int CT>   // 8 (DP=64) or 6 (DP=48)
__device__ __forceinline__ void phase2(const float* xs, const float* ws,
                                       float* out, int row0) {
    constexpr int DP = 8 * CT;
    constexpr int CP = CT / 2;
    const int tid = threadIdx.x;
    const int rg = tid >> 3, cg = tid & 7;

    unsigned long long acc[8][CP];
#pragma unroll
    for (int m = 0; m < 8; m++)
#pragma unroll
        for (int p = 0; p < CP; p++) acc[m][p] = 0ULL;

#pragma unroll 4
    for (int k = 0; k < 64; k++) {
        unsigned long long xp[8];
#pragma unroll
        for (int m = 0; m < 8; m++)
            xp[m] = pack2(xs[(rg + 32 * m) * 68 + k]);
        const unsigned long long* wp =
            (const unsigned long long*)&ws[k * DP + cg * CT];
        unsigned long long wv[CP];
#pragma unroll
        for (int p = 0; p < CP; p++) wv[p] = wp[p];
#pragma unroll
        for (int m = 0; m < 8; m++)
#pragma unroll
            for (int p = 0; p < CP; p++) ffma2(acc[m][p], xp[m], wv[p]);
    }

#pragma unroll
    for (int m = 0; m < 8; m++) {
        int gr = row0 + rg + 32 * m;
        if (gr < NN) {
            unsigned long long* o =
                (unsigned long long*)(out + (size_t)gr * DP + cg * CT);
#pragma unroll
            for (int p = 0; p < CP; p++) o[p] = acc[m][p];
        }
    }
}

template <int DP>
__device__ __forceinline__ void stage_w(float* ws, const float* __restrict__ W,
                                        int wcols) {
    for (int i = threadIdx.x; i < 64 * DP; i += 256) {
        int k = i / DP, c = i - k * DP;
        ws[i] = (c < wcols) ? W[k * wcols + c] : 0.f;
    }
}

// ---------------------------------------------------------------------------
// GEMM: blk_base allows chunked launches. ZP: zero the 48-wide pad row.
// ---------------------------------------------------------------------------
template <int CT, bool ZP>
__global__ void gemm_kernel(const float* __restrict__ in,
                            const float* __restrict__ W, int wcols,
                            float* __restrict__ out, int blk_base) {
    constexpr int DP = 8 * CT;
    extern __shared__ float smem[];
    float* xs = smem;                // 256 rows x stride 68
    float* ws = smem + 256 * 68;     // 64 x DP

    if (ZP && blk_base == 0 && blockIdx.x == 0 && threadIdx.x < 48)
        out[(size_t)NN * 48 + threadIdx.x] = 0.f;

    stage_w<DP>(ws, W, wcols);
    const int row0 = (blockIdx.x + blk_base) * 256;
    for (int i = threadIdx.x; i < 256 * 16; i += 256) {
        int r = i >> 4, c4 = i & 15;
        int gr = row0 + r;
        float4 v = (gr < NN) ? ((const float4*)in)[(size_t)gr * 16 + c4]
                             : make_float4(0.f, 0.f, 0.f, 0.f);
        *(float4*)&xs[r * 68 + c4 * 4] = v;
    }
    __syncthreads();
    phase2<CT>(xs, ws, out, row0);
}

// ---------------------------------------------------------------------------
// Gather (chunked): out[n] = epi(bias + sum_{e in bkt[n]} h[src[e]]), nodes
// n in [base, base+cnt). deg pre-padded to 8; pad entries point at zero row.
// Single uniform 8-batch loop — no remainder, no divergence.
// ---------------------------------------------------------------------------
template <int CH, bool LSM>
__global__ void gather_kernel(const float* __restrict__ h,
                              const float* __restrict__ bias, int bcols,
                              float* __restrict__ outp, int base, int cnt) {
    int t = blockIdx.x * blockDim.x + threadIdx.x;
    int g = t >> 4;
    if (g >= cnt) return;
    int n  = base + g;
    int ln = t & 15;

    const bool act = (ln < CH);
    float4 a = make_float4(0.f, 0.f, 0.f, 0.f);
    float4 b = a;
    if (act) {
        int c = ln * 4;
        a.x = bias[c];
        a.y = bias[c + 1];
        a.z = bias[c + 2];
        a.w = (c + 3 < bcols) ? bias[c + 3] : 0.f;
    }

    int deg8 = g_deg[n];
    const int* bp = &g_bkt[(size_t)n * BCAP];
    const float4* h4 = (const float4*)h;

    for (int e = 0; e < deg8; e += 8) {
        int4 i0 = *(const int4*)(bp + e);
        int4 i1 = *(const int4*)(bp + e + 4);
        if (act) {
            float4 v0 = h4[(size_t)i0.x * CH + ln];
            float4 v1 = h4[(size_t)i0.y * CH + ln];
            float4 v2 = h4[(size_t)i0.z * CH + ln];
            float4 v3 = h4[(size_t)i0.w * CH + ln];
            float4 v4 = h4[(size_t)i1.x * CH + ln];
            float4 v5 = h4[(size_t)i1.y * CH + ln];
            float4 v6 = h4[(size_t)i1.z * CH + ln];
            float4 v7 = h4[(size_t)i1.w * CH + ln];
            a.x += (v0.x + v1.x) + (v2.x + v3.x);
            a.y += (v0.y + v1.y) + (v2.y + v3.y);
            a.z += (v0.z + v1.z) + (v2.z + v3.z);
            a.w += (v0.w + v1.w) + (v2.w + v3.w);
            b.x += (v4.x + v5.x) + (v6.x + v7.x);
            b.y += (v4.y + v5.y) + (v6.y + v7.y);
            b.z += (v4.z + v5.z) + (v6.z + v7.z);
            b.w += (v4.w + v5.w) + (v6.w + v7.w);
        }
    }
    a.x += b.x; a.y += b.y; a.z += b.z; a.w += b.w;

    if (!LSM) {
        a.x = fmaxf(a.x, 0.f); a.y = fmaxf(a.y, 0.f);
        a.z = fmaxf(a.z, 0.f); a.w = fmaxf(a.w, 0.f);
        if (act) ((float4*)outp)[(size_t)n * CH + ln] = a;
    } else {
        float e0 = a.x, e1 = a.y, e2 = a.z, e3 = a.w;
        bool v3ok = (ln * 4 + 3 < DOUT);
        if (!act)       { e0 = e1 = e2 = e3 = -INFINITY; }
        else if (!v3ok) { e3 = -INFINITY; }

        float m = fmaxf(fmaxf(e0, e1), fmaxf(e2, e3));
#pragma unroll
        for (int off = 8; off; off >>= 1)
            m = fmaxf(m, __shfl_xor_sync(0xFFFFFFFFu, m, off));

        float s = 0.f;
        if (act) {
            s = expf(e0 - m) + expf(e1 - m) + expf(e2 - m);
            if (v3ok) s += expf(e3 - m);
        }
#pragma unroll
        for (int off = 8; off; off >>= 1)
            s += __shfl_xor_sync(0xFFFFFFFFu, s, off);

        float lse = m + logf(s);
        if (act) {
            size_t o = (size_t)n * DOUT + ln * 4;
            outp[o]     = e0 - lse;
            outp[o + 1] = e1 - lse;
            outp[o + 2] = e2 - lse;
            if (v3ok) outp[o + 3] = e3 - lse;
        }
    }
}

// ---------------------------------------------------------------------------
extern "C" void kernel_launch(void* const* d_in, const int* in_sizes, int n_in,
                              void* d_out, int out_size) {
    const float* x  = (const float*)d_in[0];
    const void*  ei = d_in[1];
    const float* W1 = (const float*)d_in[2];
    const float* b1 = (const float*)d_in[3];
    const float* W2 = (const float*)d_in[4];
    const float* b2 = (const float*)d_in[5];
    const float* W3 = (const float*)d_in[6];
    const float* b3 = (const float*)d_in[7];
    float* out = (float*)d_out;

    float *h_ptr, *h2_ptr, *agg_ptr;
    cudaGetSymbolAddress((void**)&h_ptr,  g_h);
    cudaGetSymbolAddress((void**)&h2_ptr, g_h2);
    cudaGetSymbolAddress((void**)&agg_ptr, g_agg);

    const int SM64 = (256 * 68 + 64 * 64) * 4;  // 86016
    const int SM48 = (256 * 68 + 64 * 48) * 4;  // 81920

    static cudaStream_t s2 = nullptr;
    static cudaEvent_t evFork, evJoin, evB, evD, evA[4], evC[4];
    if (!s2) {
        cudaFuncSetAttribute(gemm_kernel<8, false>,
                             cudaFuncAttributeMaxDynamicSharedMemorySize, SM64);
        cudaFuncSetAttribute(gemm_kernel<6, true>,
                             cudaFuncAttributeMaxDynamicSharedMemorySize, SM48);
        cudaStreamCreateWithFlags(&s2, cudaStreamNonBlocking);
        cudaEventCreateWithFlags(&evFork, cudaEventDisableTiming);
        cudaEventCreateWithFlags(&evJoin, cudaEventDisableTiming);
        cudaEventCreateWithFlags(&evB, cudaEventDisableTiming);
        cudaEventCreateWithFlags(&evD, cudaEventDisableTiming);
        for (int c = 0; c < 4; c++) {
            cudaEventCreateWithFlags(&evA[c], cudaEventDisableTiming);
            cudaEventCreateWithFlags(&evC[c], cudaEventDisableTiming);
        }
    }

    const int GEMM_BLKS = (NN + 255) / 256;                    // 391
    const int EDGE_BLKS = (EE + 255) / 256;                    // 3125
    const int NODE_BLKS = (NN + 255) / 256;                    // 391
    const int GATH_BLKS = ((long long)NN * 16 + 255) / 256;    // 6250

    // Chunk geometry: 3 x 25600 + 23200
    const int cbase[4] = {0, CHK, 2 * CHK, 3 * CHK};
    const int ccnt[4]  = {CHK, CHK, CHK, NN - 3 * CHK};
    const int cgath[4] = {CHK / 16, CHK / 16, CHK / 16, (NN - 3 * CHK) / 16};
    const int cgemm[4] = {CHK / 256, CHK / 256, CHK / 256,
                          (NN - 3 * CHK + 255) / 256};   // 100,100,100,91
    const int cblk0[4] = {0, 100, 200, 300};

    // --- Fork: bucket build + padding on s2, concurrent with layer-1 GEMM ---
    cudaEventRecord(evFork, 0);
    cudaStreamWaitEvent(s2, evFork, 0);
    zero_detect_kernel<<<NODE_BLKS, 256, 0, s2>>>(ei);
    bucket_fill_kernel<<<EDGE_BLKS, 256, 0, s2>>>(ei);
    pad_kernel<<<NODE_BLKS, 256, 0, s2>>>();
    cudaEventRecord(evJoin, s2);

    // Layer-1 GEMM (full) on main stream: g_h = x @ W1
    gemm_kernel<8, false><<<GEMM_BLKS, 256, SM64>>>(x, W1, 64, h_ptr, 0);
    cudaStreamWaitEvent(0, evJoin, 0);

    // --- Boundary A: gather1 chunks (main) pipelined with gemm2 chunks (s2)
    //     gather1: agg = relu(gather(g_h) + b1);  gemm2: g_h2 = agg @ W2
    for (int c = 0; c < 4; c++) {
        gather_kernel<16, false><<<cgath[c], 256>>>(h_ptr, b1, 64, agg_ptr,
                                                    cbase[c], ccnt[c]);
        cudaEventRecord(evA[c], 0);
        cudaStreamWaitEvent(s2, evA[c], 0);
        gemm_kernel<8, false><<<cgemm[c], 256, SM64, s2>>>(agg_ptr, W2, 64,
                                                           h2_ptr, cblk0[c]);
    }
    cudaEventRecord(evB, s2);
    cudaStreamWaitEvent(0, evB, 0);

    // --- Boundary B: gather2 chunks (main) pipelined with gemm3 chunks (s2)
    //     gather2: agg = relu(gather(g_h2) + b2);  gemm3: g_h(48w) = agg @ W3
    for (int c = 0; c < 4; c++) {
        gather_kernel<16, false><<<cgath[c], 256>>>(h2_ptr, b2, 64, agg_ptr,
                                                    cbase[c], ccnt[c]);
        cudaEventRecord(evC[c], 0);
        cudaStreamWaitEvent(s2, evC[c], 0);
        gemm_kernel<6, true><<<cgemm[c], 256, SM48, s2>>>(agg_ptr, W3, 47,
                                                          h_ptr, cblk0[c]);
    }
    cudaEventRecord(evD, s2);
    cudaStreamWaitEvent(0, evD, 0);

    // --- Final: out = log_softmax(gather(g_h 48w) + b3)
    gather_kernel<12, true><<<GATH_BLKS, 256>>>(h_ptr, b3, 47, out, 0, NN);
}

// round 8
// speedup vs baseline: 1.3576x; 1.3576x over previous
#include <cuda_runtime.h>
#include <math.h>

#define NN 100000
#define EE 800000
#define DOUT 47
#define BCAP 64

// Scratch (allocation-free rule: static device globals).
// g_h / g_h2 have one extra row (index NN) used as an all-zero gather target
// for bucket padding.
__device__ float g_h [(size_t)(NN + 1) * 64];
__device__ float g_h2[(size_t)(NN + 1) * 64];
__device__ float g_agg[(size_t)NN * 64];
__device__ int   g_deg[NN];          // after pad_kernel: deg rounded up to 8
__device__ int   g_bkt[(size_t)NN * BCAP];
__device__ int   g_idx64;

// ---------------------------------------------------------------------------
// Packed fp32x2 FMA (Blackwell FFMA2 — only reachable via PTX)
// ---------------------------------------------------------------------------
__device__ __forceinline__ void ffma2(unsigned long long& acc,
                                      unsigned long long a,
                                      unsigned long long b) {
    asm("fma.rn.f32x2 %0, %1, %2, %0;" : "+l"(acc) : "l"(a), "l"(b));
}
__device__ __forceinline__ unsigned long long pack2(float x) {
    unsigned long long r;
    asm("mov.b64 %0, {%1, %2};" : "=l"(r) : "f"(x), "f"(x));
    return r;
}

// ---------------------------------------------------------------------------
// zero degree array + detect edge dtype + zero the padding rows of g_h/g_h2
// ---------------------------------------------------------------------------
__global__ void zero_detect_kernel(const void* ei) {
    int i = blockIdx.x * blockDim.x + threadIdx.x;
    if (i < NN) g_deg[i] = 0;
    if (blockIdx.x == 0) {
        __shared__ int bad;
        if (threadIdx.x == 0) bad = 0;
        __syncthreads();
        const long long* p = (const long long*)ei;
        for (int j = threadIdx.x; j < 4096; j += blockDim.x) {
            long long v = p[j];
            if (v < 0 || v >= NN) bad = 1;
        }
        __syncthreads();
        if (threadIdx.x == 0) g_idx64 = bad ? 0 : 1;
    }
    if (blockIdx.x == 1 && threadIdx.x < 64) {
        g_h [(size_t)NN * 64 + threadIdx.x] = 0.f;
        g_h2[(size_t)NN * 64 + threadIdx.x] = 0.f;
    }
}

// ---------------------------------------------------------------------------
// Bucket fill: bkt[dst][pos++] = src
// ---------------------------------------------------------------------------
__global__ void bucket_fill_kernel(const void* ei) {
    int e = blockIdx.x * blockDim.x + threadIdx.x;
    if (e >= EE) return;
    int src, dst;
    if (g_idx64) {
        const long long* p = (const long long*)ei;
        src = (int)p[e];
        dst = (int)p[EE + e];
    } else {
        const int* p = (const int*)ei;
        src = p[e];
        dst = p[EE + e];
    }
    int pos = atomicAdd(&g_deg[dst], 1);
    if (pos < BCAP) g_bkt[(size_t)dst * BCAP + pos] = src;
}

// ---------------------------------------------------------------------------
// Pad each bucket to a multiple of 8 with sentinel NN (zero row); store deg8.
// ---------------------------------------------------------------------------
__global__ void pad_kernel() {
    int i = blockIdx.x * blockDim.x + threadIdx.x;
    if (i >= NN) return;
    int d  = min(g_deg[i], BCAP);
    int d8 = (d + 7) & ~7;
    int* bp = &g_bkt[(size_t)i * BCAP];
    for (int j = d; j < d8; j++) bp[j] = NN;
    g_deg[i] = d8;
}

// ---------------------------------------------------------------------------
// GEMM: out[*, 0..DP) = in[*, 0..63] @ W[64, wcols] (zero-padded to DP).
// 128-row tile, 256 threads, 4 blocks/SM (51KB smem). Thread (rg=tid>>3,
// cg=tid&7): rows rg+{0,32,64,96}, cols quad [cg*4) + (DP==64 ? quad [32+cg*4)
// : pair [32+cg*2)). W via LDS.128 (conflict-free), x scalar broadcast.
// ZP: zero the 48-wide pad row for the LSM gather.
// ---------------------------------------------------------------------------
template <int DP, bool ZP>   // DP = 64 or 48
__global__ void __launch_bounds__(256, 4)
gemm_kernel(const float* __restrict__ in, const float* __restrict__ W,
            int wcols, float* __restrict__ out, int blk_base) {
    constexpr int NA = (DP == 64) ? 4 : 3;   // ull accumulators per row
    extern __shared__ float smem[];
    float* xs = smem;                 // 128 rows x stride 68
    float* ws = smem + 128 * 68;      // 64 x DP

    const int tid = threadIdx.x;
    if (ZP && blk_base == 0 && blockIdx.x == 0 && tid < 48)
        out[(size_t)NN * 48 + tid] = 0.f;

    for (int i = tid; i < 64 * DP; i += 256) {
        int k = i / DP, c = i - k * DP;
        ws[i] = (c < wcols) ? W[k * wcols + c] : 0.f;
    }
    const int row0 = (blockIdx.x + blk_base) * 128;
    for (int i = tid; i < 128 * 16; i += 256) {
        int r = i >> 4, c4 = i & 15;
        int gr = row0 + r;
        float4 v = (gr < NN) ? ((const float4*)in)[(size_t)gr * 16 + c4]
                             : make_float4(0.f, 0.f, 0.f, 0.f);
        *(float4*)&xs[r * 68 + c4 * 4] = v;
    }
    __syncthreads();

    const int rg = tid >> 3;
    const int cg = tid & 7;

    unsigned long long acc[4][NA];
#pragma unroll
    for (int m = 0; m < 4; m++)
#pragma unroll
        for (int j = 0; j < NA; j++) acc[m][j] = 0ULL;

    const float* xr = &xs[rg * 68];

#pragma unroll 8
    for (int k = 0; k < 64; k++) {
        unsigned long long xp[4];
#pragma unroll
        for (int m = 0; m < 4; m++)
            xp[m] = pack2(xr[m * (32 * 68) + k]);

        ulonglong2 w1 = *(const ulonglong2*)&ws[k * DP + cg * 4];
        if (DP == 64) {
            ulonglong2 w2 = *(const ulonglong2*)&ws[k * DP + 32 + cg * 4];
#pragma unroll
            for (int m = 0; m < 4; m++) {
                ffma2(acc[m][0], xp[m], w1.x);
                ffma2(acc[m][1], xp[m], w1.y);
                ffma2(acc[m][2], xp[m], w2.x);
                ffma2(acc[m][3], xp[m], w2.y);
            }
        } else {
            unsigned long long w2 =
                *(const unsigned long long*)&ws[k * DP + 32 + cg * 2];
#pragma unroll
            for (int m = 0; m < 4; m++) {
                ffma2(acc[m][0], xp[m], w1.x);
                ffma2(acc[m][1], xp[m], w1.y);
                ffma2(acc[m][2], xp[m], w2);
            }
        }
    }

#pragma unroll
    for (int m = 0; m < 4; m++) {
        int gr = row0 + rg + 32 * m;
        if (gr < NN) {
            *(ulonglong2*)&out[(size_t)gr * DP + cg * 4] =
                make_ulonglong2(acc[m][0], acc[m][1]);
            if (DP == 64) {
                *(ulonglong2*)&out[(size_t)gr * DP + 32 + cg * 4] =
                    make_ulonglong2(acc[m][2], acc[m][3]);
            } else {
                *(unsigned long long*)&out[(size_t)gr * DP + 32 + cg * 2] =
                    acc[m][2];
            }
        }
    }
}

// ---------------------------------------------------------------------------
// Gather: out[n] = epi(bias + sum_{e in bkt[n]} h[src[e]]). 16 lanes/node.
// deg pre-padded to 8 (pad entries -> zero row): uniform 8-batch loop.
// ---------------------------------------------------------------------------
template <int CH, bool LSM>
__global__ void gather_kernel(const float* __restrict__ h,
                              const float* __restrict__ bias, int bcols,
                              float* __restrict__ outp) {
    int t = blockIdx.x * blockDim.x + threadIdx.x;
    int n = t >> 4;
    if (n >= NN) return;
    int ln = t & 15;

    const bool act = (ln < CH);
    float4 a = make_float4(0.f, 0.f, 0.f, 0.f);
    float4 b = a;
    if (act) {
        int c = ln * 4;
        a.x = bias[c];
        a.y = bias[c + 1];
        a.z = bias[c + 2];
        a.w = (c + 3 < bcols) ? bias[c + 3] : 0.f;
    }

    int deg8 = g_deg[n];
    const int* bp = &g_bkt[(size_t)n * BCAP];
    const float4* h4 = (const float4*)h;

    for (int e = 0; e < deg8; e += 8) {
        int4 i0 = *(const int4*)(bp + e);
        int4 i1 = *(const int4*)(bp + e + 4);
        if (act) {
            float4 v0 = h4[(size_t)i0.x * CH + ln];
            float4 v1 = h4[(size_t)i0.y * CH + ln];
            float4 v2 = h4[(size_t)i0.z * CH + ln];
            float4 v3 = h4[(size_t)i0.w * CH + ln];
            float4 v4 = h4[(size_t)i1.x * CH + ln];
            float4 v5 = h4[(size_t)i1.y * CH + ln];
            float4 v6 = h4[(size_t)i1.z * CH + ln];
            float4 v7 = h4[(size_t)i1.w * CH + ln];
            a.x += (v0.x + v1.x) + (v2.x + v3.x);
            a.y += (v0.y + v1.y) + (v2.y + v3.y);
            a.z += (v0.z + v1.z) + (v2.z + v3.z);
            a.w += (v0.w + v1.w) + (v2.w + v3.w);
            b.x += (v4.x + v5.x) + (v6.x + v7.x);
            b.y += (v4.y + v5.y) + (v6.y + v7.y);
            b.z += (v4.z + v5.z) + (v6.z + v7.z);
            b.w += (v4.w + v5.w) + (v6.w + v7.w);
        }
    }
    a.x += b.x; a.y += b.y; a.z += b.z; a.w += b.w;

    if (!LSM) {
        a.x = fmaxf(a.x, 0.f); a.y = fmaxf(a.y, 0.f);
        a.z = fmaxf(a.z, 0.f); a.w = fmaxf(a.w, 0.f);
        if (act) ((float4*)outp)[(size_t)n * CH + ln] = a;
    } else {
        float e0 = a.x, e1 = a.y, e2 = a.z, e3 = a.w;
        bool v3ok = (ln * 4 + 3 < DOUT);
        if (!act)       { e0 = e1 = e2 = e3 = -INFINITY; }
        else if (!v3ok) { e3 = -INFINITY; }

        float m = fmaxf(fmaxf(e0, e1), fmaxf(e2, e3));
#pragma unroll
        for (int off = 8; off; off >>= 1)
            m = fmaxf(m, __shfl_xor_sync(0xFFFFFFFFu, m, off));

        float s = 0.f;
        if (act) {
            s = expf(e0 - m) + expf(e1 - m) + expf(e2 - m);
            if (v3ok) s += expf(e3 - m);
        }
#pragma unroll
        for (int off = 8; off; off >>= 1)
            s += __shfl_xor_sync(0xFFFFFFFFu, s, off);

        float lse = m + logf(s);
        if (act) {
            size_t o = (size_t)n * DOUT + ln * 4;
            outp[o]     = e0 - lse;
            outp[o + 1] = e1 - lse;
            outp[o + 2] = e2 - lse;
            if (v3ok) outp[o + 3] = e3 - lse;
        }
    }
}

// ---------------------------------------------------------------------------
extern "C" void kernel_launch(void* const* d_in, const int* in_sizes, int n_in,
                              void* d_out, int out_size) {
    const float* x  = (const float*)d_in[0];
    const void*  ei = d_in[1];
    const float* W1 = (const float*)d_in[2];
    const float* b1 = (const float*)d_in[3];
    const float* W2 = (const float*)d_in[4];
    const float* b2 = (const float*)d_in[5];
    const float* W3 = (const float*)d_in[6];
    const float* b3 = (const float*)d_in[7];
    float* out = (float*)d_out;

    float *h_ptr, *h2_ptr, *agg_ptr;
    cudaGetSymbolAddress((void**)&h_ptr,  g_h);
    cudaGetSymbolAddress((void**)&h2_ptr, g_h2);
    cudaGetSymbolAddress((void**)&agg_ptr, g_agg);

    const int SM64 = (128 * 68 + 64 * 64) * 4;  // 51200
    const int SM48 = (128 * 68 + 64 * 48) * 4;  // 47104

    static cudaStream_t s2 = nullptr;
    static cudaEvent_t evFork, evJoin;
    if (!s2) {
        cudaFuncSetAttribute(gemm_kernel<64, false>,
                             cudaFuncAttributeMaxDynamicSharedMemorySize, SM64);
        cudaFuncSetAttribute(gemm_kernel<48, true>,
                             cudaFuncAttributeMaxDynamicSharedMemorySize, SM48);
        cudaStreamCreateWithFlags(&s2, cudaStreamNonBlocking);
        cudaEventCreateWithFlags(&evFork, cudaEventDisableTiming);
        cudaEventCreateWithFlags(&evJoin, cudaEventDisableTiming);
    }

    const int GEMM_BLKS = (NN + 127) / 128;                    // 782
    const int HALF_A    = (GEMM_BLKS + 1) / 2;                 // 391
    const int HALF_B    = GEMM_BLKS - HALF_A;                  // 391
    const int EDGE_BLKS = (EE + 255) / 256;                    // 3125
    const int NODE_BLKS = (NN + 255) / 256;                    // 391
    const int GATH_BLKS = ((long long)NN * 16 + 255) / 256;    // 6250

    // --- Fork: bucket build + padding on s2, concurrent with layer-1 GEMM ---
    cudaEventRecord(evFork, 0);
    cudaStreamWaitEvent(s2, evFork, 0);
    zero_detect_kernel<<<NODE_BLKS, 256, 0, s2>>>(ei);
    bucket_fill_kernel<<<EDGE_BLKS, 256, 0, s2>>>(ei);
    pad_kernel<<<NODE_BLKS, 256, 0, s2>>>();
    cudaEventRecord(evJoin, s2);

    // Layer-1 GEMM (full) on main stream: g_h = x @ W1
    gemm_kernel<64, false><<<GEMM_BLKS, 256, SM64>>>(x, W1, 64, h_ptr, 0);
    cudaStreamWaitEvent(0, evJoin, 0);

    // Layer 1 aggregate: agg = relu(gather(g_h) + b1)
    gather_kernel<16, false><<<GATH_BLKS, 256>>>(h_ptr, b1, 64, agg_ptr);

    // Layer 2: g_h2 = agg @ W2 (split for ncu visibility); agg = relu(...)
    gemm_kernel<64, false><<<HALF_A, 256, SM64>>>(agg_ptr, W2, 64, h2_ptr, 0);
    gemm_kernel<64, false><<<HALF_B, 256, SM64>>>(agg_ptr, W2, 64, h2_ptr,
                                                  HALF_A);
    gather_kernel<16, false><<<GATH_BLKS, 256>>>(h2_ptr, b2, 64, agg_ptr);

    // Layer 3: g_h(48w) = agg @ W3 ; out = log_softmax(gather + b3)
    gemm_kernel<48, true><<<GEMM_BLKS, 256, SM48>>>(agg_ptr, W3, 47, h_ptr, 0);
    gather_kernel<12, true><<<GATH_BLKS, 256>>>(h_ptr, b3, 47, out);
}

// round 9
// speedup vs baseline: 1.4880x; 1.0960x over previous
#include <cuda_runtime.h>
#include <math.h>

#define NN 100000
#define EE 800000
#define DOUT 47
#define BCAP 64
#define GTILES 782          // 128-row tiles
#define GBLKS  391          // blocks; each does tiles b and b+391

// Scratch (allocation-free rule: static device globals).
// g_h / g_h2 have one extra row (index NN) used as an all-zero gather target
// for bucket padding.
__device__ float g_h [(size_t)(NN + 1) * 64];
__device__ float g_h2[(size_t)(NN + 1) * 64];
__device__ float g_agg[(size_t)NN * 64];
__device__ int   g_deg[NN];          // after pad_kernel: deg rounded up to 8
__device__ int   g_bkt[(size_t)NN * BCAP];
__device__ int   g_idx64;

// ---------------------------------------------------------------------------
// Packed fp32x2 FMA (Blackwell FFMA2 — only reachable via PTX)
// ---------------------------------------------------------------------------
__device__ __forceinline__ void ffma2(unsigned long long& acc,
                                      unsigned long long a,
                                      unsigned long long b) {
    asm("fma.rn.f32x2 %0, %1, %2, %0;" : "+l"(acc) : "l"(a), "l"(b));
}
__device__ __forceinline__ unsigned long long pack2(float x) {
    unsigned long long r;
    asm("mov.b64 %0, {%1, %2};" : "=l"(r) : "f"(x), "f"(x));
    return r;
}

// ---------------------------------------------------------------------------
// zero degree array + detect edge dtype + zero the padding rows of g_h/g_h2
// ---------------------------------------------------------------------------
__global__ void zero_detect_kernel(const void* ei) {
    int i = blockIdx.x * blockDim.x + threadIdx.x;
    if (i < NN) g_deg[i] = 0;
    if (blockIdx.x == 0) {
        __shared__ int bad;
        if (threadIdx.x == 0) bad = 0;
        __syncthreads();
        const long long* p = (const long long*)ei;
        for (int j = threadIdx.x; j < 4096; j += blockDim.x) {
            long long v = p[j];
            if (v < 0 || v >= NN) bad = 1;
        }
        __syncthreads();
        if (threadIdx.x == 0) g_idx64 = bad ? 0 : 1;
    }
    if (blockIdx.x == 1 && threadIdx.x < 64) {
        g_h [(size_t)NN * 64 + threadIdx.x] = 0.f;
        g_h2[(size_t)NN * 64 + threadIdx.x] = 0.f;
    }
}

// ---------------------------------------------------------------------------
// Bucket fill: bkt[dst][pos++] = src
// ---------------------------------------------------------------------------
__global__ void bucket_fill_kernel(const void* ei) {
    int e = blockIdx.x * blockDim.x + threadIdx.x;
    if (e >= EE) return;
    int src, dst;
    if (g_idx64) {
        const long long* p = (const long long*)ei;
        src = (int)p[e];
        dst = (int)p[EE + e];
    } else {
        const int* p = (const int*)ei;
        src = p[e];
        dst = p[EE + e];
    }
    int pos = atomicAdd(&g_deg[dst], 1);
    if (pos < BCAP) g_bkt[(size_t)dst * BCAP + pos] = src;
}

// ---------------------------------------------------------------------------
// Pad each bucket to a multiple of 8 with sentinel NN (zero row); store deg8.
// ---------------------------------------------------------------------------
__global__ void pad_kernel() {
    int i = blockIdx.x * blockDim.x + threadIdx.x;
    if (i >= NN) return;
    int d  = min(g_deg[i], BCAP);
    int d8 = (d + 7) & ~7;
    int* bp = &g_bkt[(size_t)i * BCAP];
    for (int j = d; j < d8; j++) bp[j] = NN;
    g_deg[i] = d8;
}

// ---------------------------------------------------------------------------
// GEMM: out[*, 0..DP) = in[*, 0..63] @ W[64, wcols] (zero-padded to DP).
// Single-wave: 391 blocks, each processes 2 x 128-row tiles (b, b+391).
// 4 blocks/SM (51KB smem). Thread (rg=tid>>3, cg=tid&7): rows rg+{0,32,64,96},
// cols quad [cg*4) + (DP==64 ? quad [32+cg*4) : pair [32+cg*2)).
// W staged once per block; LDS.128 conflict-free; x scalar broadcast.
// ZP: zero the 48-wide pad row for the LSM gather.
// ---------------------------------------------------------------------------
template <int DP, bool ZP>   // DP = 64 or 48
__global__ void __launch_bounds__(256, 4)
gemm_kernel(const float* __restrict__ in, const float* __restrict__ W,
            int wcols, float* __restrict__ out) {
    constexpr int NA = (DP == 64) ? 4 : 3;   // ull accumulators per row
    extern __shared__ float smem[];
    float* xs = smem;                 // 128 rows x stride 68
    float* ws = smem + 128 * 68;      // 64 x DP

    const int tid = threadIdx.x;
    if (ZP && blockIdx.x == 0 && tid < 48)
        out[(size_t)NN * 48 + tid] = 0.f;

    for (int i = tid; i < 64 * DP; i += 256) {
        int k = i / DP, c = i - k * DP;
        ws[i] = (c < wcols) ? W[k * wcols + c] : 0.f;
    }

    const int rg = tid >> 3;
    const int cg = tid & 7;

#pragma unroll
    for (int t = 0; t < 2; t++) {
        const int row0 = (blockIdx.x + t * GBLKS) * 128;
        if (row0 >= NN) break;

        if (t) __syncthreads();   // all reads of previous xs done
        for (int i = tid; i < 128 * 16; i += 256) {
            int r = i >> 4, c4 = i & 15;
            int gr = row0 + r;
            float4 v = (gr < NN) ? ((const float4*)in)[(size_t)gr * 16 + c4]
                                 : make_float4(0.f, 0.f, 0.f, 0.f);
            *(float4*)&xs[r * 68 + c4 * 4] = v;
        }
        __syncthreads();

        unsigned long long acc[4][NA];
#pragma unroll
        for (int m = 0; m < 4; m++)
#pragma unroll
            for (int j = 0; j < NA; j++) acc[m][j] = 0ULL;

        const float* xr = &xs[rg * 68];

#pragma unroll 8
        for (int k = 0; k < 64; k++) {
            unsigned long long xp[4];
#pragma unroll
            for (int m = 0; m < 4; m++)
                xp[m] = pack2(xr[m * (32 * 68) + k]);

            ulonglong2 w1 = *(const ulonglong2*)&ws[k * DP + cg * 4];
            if (DP == 64) {
                ulonglong2 w2 = *(const ulonglong2*)&ws[k * DP + 32 + cg * 4];
#pragma unroll
                for (int m = 0; m < 4; m++) {
                    ffma2(acc[m][0], xp[m], w1.x);
                    ffma2(acc[m][1], xp[m], w1.y);
                    ffma2(acc[m][2], xp[m], w2.x);
                    ffma2(acc[m][3], xp[m], w2.y);
                }
            } else {
                unsigned long long w2 =
                    *(const unsigned long long*)&ws[k * DP + 32 + cg * 2];
#pragma unroll
                for (int m = 0; m < 4; m++) {
                    ffma2(acc[m][0], xp[m], w1.x);
                    ffma2(acc[m][1], xp[m], w1.y);
                    ffma2(acc[m][2], xp[m], w2);
                }
            }
        }

#pragma unroll
        for (int m = 0; m < 4; m++) {
            int gr = row0 + rg + 32 * m;
            if (gr < NN) {
                *(ulonglong2*)&out[(size_t)gr * DP + cg * 4] =
                    make_ulonglong2(acc[m][0], acc[m][1]);
                if (DP == 64) {
                    *(ulonglong2*)&out[(size_t)gr * DP + 32 + cg * 4] =
                        make_ulonglong2(acc[m][2], acc[m][3]);
                } else {
                    *(unsigned long long*)&out[(size_t)gr * DP + 32 + cg * 2] =
                        acc[m][2];
                }
            }
        }
    }
}

// ---------------------------------------------------------------------------
// Gather: out[n] = epi(bias + sum_{e in bkt[n]} h[src[e]]). 16 lanes/node.
// deg pre-padded to 8 (pad entries -> zero row): uniform 8-batch loop.
// ---------------------------------------------------------------------------
template <int CH, bool LSM>
__global__ void gather_kernel(const float* __restrict__ h,
                              const float* __restrict__ bias, int bcols,
                              float* __restrict__ outp) {
    int t = blockIdx.x * blockDim.x + threadIdx.x;
    int n = t >> 4;
    if (n >= NN) return;
    int ln = t & 15;

    const bool act = (ln < CH);
    float4 a = make_float4(0.f, 0.f, 0.f, 0.f);
    float4 b = a;
    if (act) {
        int c = ln * 4;
        a.x = bias[c];
        a.y = bias[c + 1];
        a.z = bias[c + 2];
        a.w = (c + 3 < bcols) ? bias[c + 3] : 0.f;
    }

    int deg8 = g_deg[n];
    const int* bp = &g_bkt[(size_t)n * BCAP];
    const float4* h4 = (const float4*)h;

    for (int e = 0; e < deg8; e += 8) {
        int4 i0 = *(const int4*)(bp + e);
        int4 i1 = *(const int4*)(bp + e + 4);
        if (act) {
            float4 v0 = h4[(size_t)i0.x * CH + ln];
            float4 v1 = h4[(size_t)i0.y * CH + ln];
            float4 v2 = h4[(size_t)i0.z * CH + ln];
            float4 v3 = h4[(size_t)i0.w * CH + ln];
            float4 v4 = h4[(size_t)i1.x * CH + ln];
            float4 v5 = h4[(size_t)i1.y * CH + ln];
            float4 v6 = h4[(size_t)i1.z * CH + ln];
            float4 v7 = h4[(size_t)i1.w * CH + ln];
            a.x += (v0.x + v1.x) + (v2.x + v3.x);
            a.y += (v0.y + v1.y) + (v2.y + v3.y);
            a.z += (v0.z + v1.z) + (v2.z + v3.z);
            a.w += (v0.w + v1.w) + (v2.w + v3.w);
            b.x += (v4.x + v5.x) + (v6.x + v7.x);
            b.y += (v4.y + v5.y) + (v6.y + v7.y);
            b.z += (v4.z + v5.z) + (v6.z + v7.z);
            b.w += (v4.w + v5.w) + (v6.w + v7.w);
        }
    }
    a.x += b.x; a.y += b.y; a.z += b.z; a.w += b.w;

    if (!LSM) {
        a.x = fmaxf(a.x, 0.f); a.y = fmaxf(a.y, 0.f);
        a.z = fmaxf(a.z, 0.f); a.w = fmaxf(a.w, 0.f);
        if (act) ((float4*)outp)[(size_t)n * CH + ln] = a;
    } else {
        float e0 = a.x, e1 = a.y, e2 = a.z, e3 = a.w;
        bool v3ok = (ln * 4 + 3 < DOUT);
        if (!act)       { e0 = e1 = e2 = e3 = -INFINITY; }
        else if (!v3ok) { e3 = -INFINITY; }

        float m = fmaxf(fmaxf(e0, e1), fmaxf(e2, e3));
#pragma unroll
        for (int off = 8; off; off >>= 1)
            m = fmaxf(m, __shfl_xor_sync(0xFFFFFFFFu, m, off));

        float s = 0.f;
        if (act) {
            s = expf(e0 - m) + expf(e1 - m) + expf(e2 - m);
            if (v3ok) s += expf(e3 - m);
        }
#pragma unroll
        for (int off = 8; off; off >>= 1)
            s += __shfl_xor_sync(0xFFFFFFFFu, s, off);

        float lse = m + logf(s);
        if (act) {
            size_t o = (size_t)n * DOUT + ln * 4;
            outp[o]     = e0 - lse;
            outp[o + 1] = e1 - lse;
            outp[o + 2] = e2 - lse;
            if (v3ok) outp[o + 3] = e3 - lse;
        }
    }
}

// ---------------------------------------------------------------------------
extern "C" void kernel_launch(void* const* d_in, const int* in_sizes, int n_in,
                              void* d_out, int out_size) {
    const float* x  = (const float*)d_in[0];
    const void*  ei = d_in[1];
    const float* W1 = (const float*)d_in[2];
    const float* b1 = (const float*)d_in[3];
    const float* W2 = (const float*)d_in[4];
    const float* b2 = (const float*)d_in[5];
    const float* W3 = (const float*)d_in[6];
    const float* b3 = (const float*)d_in[7];
    float* out = (float*)d_out;

    float *h_ptr, *h2_ptr, *agg_ptr;
    cudaGetSymbolAddress((void**)&h_ptr,  g_h);
    cudaGetSymbolAddress((void**)&h2_ptr, g_h2);
    cudaGetSymbolAddress((void**)&agg_ptr, g_agg);

    const int SM64 = (128 * 68 + 64 * 64) * 4;  // 51200
    const int SM48 = (128 * 68 + 64 * 48) * 4;  // 47104

    static cudaStream_t s2 = nullptr;
    static cudaEvent_t evFork, evJoin;
    if (!s2) {
        cudaFuncSetAttribute(gemm_kernel<64, false>,
                             cudaFuncAttributeMaxDynamicSharedMemorySize, SM64);
        cudaFuncSetAttribute(gemm_kernel<48, true>,
                             cudaFuncAttributeMaxDynamicSharedMemorySize, SM48);
        cudaStreamCreateWithFlags(&s2, cudaStreamNonBlocking);
        cudaEventCreateWithFlags(&evFork, cudaEventDisableTiming);
        cudaEventCreateWithFlags(&evJoin, cudaEventDisableTiming);
    }

    const int EDGE_BLKS = (EE + 255) / 256;                    // 3125
    const int NODE_BLKS = (NN + 255) / 256;                    // 391
    const int GATH_BLKS = ((long long)NN * 16 + 255) / 256;    // 6250

    // --- Fork: bucket build + padding on s2, concurrent with layer-1 GEMM ---
    cudaEventRecord(evFork, 0);
    cudaStreamWaitEvent(s2, evFork, 0);
    zero_detect_kernel<<<NODE_BLKS, 256, 0, s2>>>(ei);           // launch 1
    bucket_fill_kernel<<<EDGE_BLKS, 256, 0, s2>>>(ei);           // launch 2
    pad_kernel<<<NODE_BLKS, 256, 0, s2>>>();                     // launch 3
    cudaEventRecord(evJoin, s2);

    // Layer-1 GEMM (single wave) on main stream: g_h = x @ W1
    gemm_kernel<64, false><<<GBLKS, 256, SM64>>>(x, W1, 64, h_ptr);   // 4
    cudaStreamWaitEvent(0, evJoin, 0);

    // Layer 1 aggregate: agg = relu(gather(g_h) + b1)
    gather_kernel<16, false><<<GATH_BLKS, 256>>>(h_ptr, b1, 64, agg_ptr); // 5

    // Layer 2: g_h2 = agg @ W2 (launch 6 — ncu capture target)
    gemm_kernel<64, false><<<GBLKS, 256, SM64>>>(agg_ptr, W2, 64, h2_ptr); // 6
    gather_kernel<16, false><<<GATH_BLKS, 256>>>(h2_ptr, b2, 64, agg_ptr); // 7

    // Layer 3: g_h(48w) = agg @ W3 ; out = log_softmax(gather + b3)
    gemm_kernel<48, true><<<GBLKS, 256, SM48>>>(agg_ptr, W3, 47, h_ptr);   // 8
    gather_kernel<12, true><<<GATH_BLKS, 256>>>(h_ptr, b3, 47, out);       // 9
}